// round 9
// baseline (speedup 1.0000x reference)
#include <cuda_runtime.h>
#include <stdint.h>

#define TT 3
#define FF 17
#define NN 8
#define DT 0.2f
#define EPS 1e-8f

#define AG 256                 // agents per tile
#define NROW 136               // floats per agent in nei (8*17)
#define EROW 51                // floats per agent in ego (3*17)
#define SST 33                 // snei stride per agent (32 used + 1 pad)

// dynamic smem layout (floats):
//   st[3*32] | sA[3*33] | sC[3*33] | sdl[8] | pad | snei[2][AG*SST]
#define OFF_ST   0
#define OFF_SA   96
#define OFF_SC   195
#define OFF_SDL  294
#define OFF_NEI  304
#define SMEM_FLOATS (OFF_NEI + 2 * AG * SST)

__device__ __forceinline__ void cp4(uint32_t dst, const float* src) {
    asm volatile("cp.async.ca.shared.global [%0], [%1], 4;" :: "r"(dst), "l"(src));
}
__device__ __forceinline__ void cp_commit() {
    asm volatile("cp.async.commit_group;" ::: "memory");
}
template<int N>
__device__ __forceinline__ void cp_wait() {
    asm volatile("cp.async.wait_group %0;" :: "n"(N) : "memory");
}

// Branchless count of sorted thresholds <= x (k in [0,32]), then 1 FMA.
__device__ __forceinline__ float pwl_eval(const float* __restrict__ t,
                                          const float* __restrict__ A,
                                          const float* __restrict__ C,
                                          float x)
{
    int k = 0;
    if (t[15]    <= x) k  = 16;
    if (t[k + 7] <= x) k += 8;
    if (t[k + 3] <= x) k += 4;
    if (t[k + 1] <= x) k += 2;
    if (t[k]     <= x) k += 1;   // k in [0,31]
    if (t[31]    <= x) k += 1;   // all <= x  => k = 32
    return fmaf(A[k], x, C[k]);
}

// Warp-cooperative gather of one tile's compacted nei fields into smem via
// cp.async. Lane-constant offsets: lane l -> neighbor l>>2, field 2+(l&3).
// One warp stages 32 agents; ~5 L1 wavefronts per agent (488B span).
__device__ __forceinline__ void stage_tile(const float* __restrict__ nei,
                                           int tile, float* dst,
                                           int warp, int lane, int n_batch)
{
    int agent0 = tile * AG + warp * 32;
    int nOff = (lane >> 2) * FF + 2 + (lane & 3);
    const float* src = nei + (size_t)agent0 * NROW + nOff;
    uint32_t d = (uint32_t)__cvta_generic_to_shared(dst + (warp * 32) * SST + lane);
#pragma unroll 8
    for (int a = 0; a < 32; a++) {
        if (agent0 + a < n_batch)
            cp4(d + (uint32_t)(a * SST * 4), src + (size_t)a * NROW);
    }
}

__global__ void __launch_bounds__(256) sfm_fused(
    const float* __restrict__ ego, const float* __restrict__ nei,
    const float* __restrict__ border, const float* __restrict__ adp,
    const float* __restrict__ eff_angle,
    const float* __restrict__ an_wi, const float* __restrict__ an_bi,
    const float* __restrict__ an_wo, const float* __restrict__ an_bo,
    const float* __restrict__ rn_wi, const float* __restrict__ rn_bi,
    const float* __restrict__ rn_wo, const float* __restrict__ rn_bo,
    const float* __restrict__ rb_wi, const float* __restrict__ rb_bi,
    const float* __restrict__ rb_wo, const float* __restrict__ rb_bo,
    const float* __restrict__ dl_wi, const float* __restrict__ dl_bi,
    const float* __restrict__ dl_wo, const float* __restrict__ dl_bo,
    float* __restrict__ out, int n_batch)
{
    extern __shared__ float dyn[];
    float* st   = dyn + OFF_ST;     // [3][32]
    float* sA   = dyn + OFF_SA;     // [3][33]
    float* sC   = dyn + OFF_SC;     // [3][33]
    float* sdl  = dyn + OFF_SDL;    // [8]
    float* snei = dyn + OFF_NEI;    // [2][AG*SST]

    int tid = threadIdx.x, warp = tid >> 5, lane = tid & 31;
    int tiles = (n_batch + AG - 1) / AG;
    const unsigned FULL = 0xffffffffu;
    const float PINF = __int_as_float(0x7f800000);

    // ---- prologue: start DMA for this block's first tile immediately ----
    int t0 = blockIdx.x;
    if (t0 < tiles) stage_tile(nei, t0, snei, warp, lane, n_batch);
    cp_commit();

    // ---- build PWL tables + dl constants (overlaps prologue DMA) ----
    if (warp < 3) {
        const float* wi = (warp == 0) ? an_wi : (warp == 1) ? rn_wi : rb_wi;
        const float* bi = (warp == 0) ? an_bi : (warp == 1) ? rn_bi : rb_bi;
        const float* wo = (warp == 0) ? an_wo : (warp == 1) ? rn_wo : rb_wo;
        const float* bo = (warp == 0) ? an_bo : (warp == 1) ? rn_bo : rb_bo;

        float wiv = wi[lane], biv = bi[lane], wov = wo[lane];
        float bov = bo[0];
        // relu(-(wi*x+bi)) active iff x < t  (wi uniform >= 0)
        float t, slope, icept;
        if (wiv > 0.f) {
            t = -biv / wiv; slope = -wov * wiv; icept = -wov * biv;
        } else if (biv < 0.f) {
            t = PINF; slope = 0.f; icept = -wov * biv;   // always active
        } else {
            t = -PINF; slope = 0.f; icept = 0.f;         // never active
        }

        // rank-sort ascending (ties by lane)
        int rank = 0;
#pragma unroll
        for (int i = 0; i < 32; i++) {
            float ti = __shfl_sync(FULL, t, i);
            rank += (ti < t) || (ti == t && i < lane);
        }
        st[warp * 32 + rank] = t;
        sA[warp * 33 + rank] = slope;   // scratch
        sC[warp * 33 + rank] = icept;   // scratch
        __syncwarp();
        float A = sA[warp * 33 + lane];
        float C = sC[warp * 33 + lane];
        // inclusive suffix scan
#pragma unroll
        for (int off = 1; off < 32; off <<= 1) {
            float a2 = __shfl_down_sync(FULL, A, off);
            float c2 = __shfl_down_sync(FULL, C, off);
            if (lane + off < 32) { A += a2; C += c2; }
        }
        C += bov;
        __syncwarp();
        sA[warp * 33 + lane] = A;
        sC[warp * 33 + lane] = C;
        if (lane == 0) { sA[warp * 33 + 32] = 0.f; sC[warp * 33 + 32] = bov; }
    } else if (warp == 3 && lane < 8) {
        // dl MLP on dur[n] (depends only on ego batch row 1)
        const float* e1 = ego + (size_t)1 * EROW;
        float id = e1[(TT - 1) * FF + 8 + lane];
        float dur = 0.f;
#pragma unroll
        for (int t = 0; t < TT; t++) {
            bool found = false;
#pragma unroll
            for (int k = 0; k < 8; k++)
                found = found || (e1[t * FF + 8 + k] == id);
            dur += found ? 1.f : 0.f;
        }
        float acc = dl_bo[0];
#pragma unroll
        for (int j = 0; j < 32; j++) {
            float h = fmaxf(-fmaf(dl_wi[j], dur, dl_bi[j]), 0.f);
            acc = fmaf(dl_wo[j], h, acc);
        }
        sdl[lane] = acc;
    }

    // uniform scalars
    float bd0 = border[0], bd3 = border[3];
    float p0 = adp[0], p1 = adp[1];
    float effv = eff_angle[0];

    // ---- software-pipelined tile loop ----
    int buf = 0;
    for (int t = t0; t < tiles; t += gridDim.x) {
        int tn = t + gridDim.x;
        bool have_next = (tn < tiles);
        if (have_next) stage_tile(nei, tn, snei + (buf ^ 1) * (AG * SST),
                                  warp, lane, n_batch);
        cp_commit();
        if (have_next) cp_wait<1>(); else cp_wait<0>();
        __syncthreads();   // staged data + tables visible

        int b = t * AG + tid;
        if (b < n_batch) {
            // ego_last fields 0..5 (scalar direct loads, front-batched)
            const float* eg = ego + (size_t)b * EROW + (TT - 1) * FF;
            float g0 = eg[0], g1 = eg[1], g2 = eg[2],
                  g3 = eg[3], g4 = eg[4], g5 = eg[5];

            float einv = rsqrtf(g4 * g4 + g5 * g5);
            float ex = g4 * einv, ey = g5 * einv;
            float na = fmaxf(sqrtf(ex * ex + ey * ey), EPS);
            float thr = effv * na;

            float ax = 0.f, ay = 0.f;

            // f_dest: v34 = (g3, g4); dv = (|v34|, 0)
            {
                float nv = sqrtf(g3 * g3 + g4 * g4);
                float fx = (p1 * nv - g3) / p0;
                float fy = (0.f - g4) / p0;
                float dot = ex * fx + ey * fy;
                float nbn = fmaxf(sqrtf(fx * fx + fy * fy), EPS);
                bool keep = fabsf(dot) > thr * nbn;
                ax += keep ? fx : 0.f;
                ay += keep ? fy : 0.f;
            }

            // neighbors from staged smem
            const float* sn = snei + buf * (AG * SST) + tid * SST;
#pragma unroll
            for (int n = 0; n < 8; n++) {
                float a2 = sn[n * 4 + 0], a3 = sn[n * 4 + 1];
                float a4 = sn[n * 4 + 2], a5 = sn[n * 4 + 3];

                bool mx = (a2 == 0.f), my = (a3 == 0.f);
                float rx = a2 - g2, ry = a3 - g3;
                float rnm = sqrtf(rx * rx + ry * ry);
                float vx = a4 * DT, vy = a5 * DT;
                float px = rx + vx, py = ry + vy;
                float bbv = sqrtf(rnm + px * px + py * py - vx * vx - vy * vy) * 0.5f;

                float fa = pwl_eval(st, sA, sC, rnm);                 // an
                float fr = pwl_eval(st + 32, sA + 33, sC + 33, bbv);  // rn
                float s = (fa * sdl[n] + fr) / rnm;

                float fxb = mx ? 0.f : rx;
                float fyb = my ? 0.f : ry;
                float dot = ex * fxb + ey * fyb;
                float nbn = sqrtf(fxb * fxb + fyb * fyb);
                bool keep = fabsf(dot) > thr * nbn;
                ax += keep ? s * fxb : 0.f;
                ay += keep ? s * fyb : 0.f;
            }

            // f_bor
            {
                float rbv0 = g3 - bd0;
                float rbv1 = g3 - bd3;
                float rbn0 = fabsf(rbv0), rbn1 = fabsf(rbv1);

                float m0 = pwl_eval(st + 64, sA + 66, sC + 66, rbn0);
                float m1 = pwl_eval(st + 64, sA + 66, sC + 66, rbn1);

                float fy0 = m0 * (rbv0 / rbn0);
                float nbn0 = fmaxf(fabsf(fy0), EPS);
                if (fabsf(ey * fy0) > thr * nbn0) ay += fy0;

                float fy1 = m1 * (rbv1 / rbn1);
                float nbn1 = fmaxf(fabsf(fy1), EPS);
                if (fabsf(ey * fy1) > thr * nbn1) ay += fy1;
            }

            float vxo = g2 + ax * DT;
            float vyo = g3 + ay * DT;
            float sx = g0 + vxo * DT;
            float sy = g1 + vyo * DT;

            float* o = out + (size_t)b * 6;   // scalar stores only
            o[0] = sx; o[1] = sy;
            o[2] = vxo; o[3] = vyo;
            o[4] = ax;  o[5] = ay;
        }

        buf ^= 1;
        __syncthreads();   // buffer consumed before next stage overwrites it
    }
}

extern "C" void kernel_launch(void* const* d_in, const int* in_sizes, int n_in,
                              void* d_out, int out_size)
{
    const float* ego    = (const float*)d_in[0];
    const float* nei    = (const float*)d_in[1];
    const float* border = (const float*)d_in[2];
    const float* adp    = (const float*)d_in[3];
    const float* eff    = (const float*)d_in[4];
    const float* an_wi  = (const float*)d_in[5];
    const float* an_bi  = (const float*)d_in[6];
    const float* an_wo  = (const float*)d_in[7];
    const float* an_bo  = (const float*)d_in[8];
    const float* rn_wi  = (const float*)d_in[9];
    const float* rn_bi  = (const float*)d_in[10];
    const float* rn_wo  = (const float*)d_in[11];
    const float* rn_bo  = (const float*)d_in[12];
    const float* rb_wi  = (const float*)d_in[13];
    const float* rb_bi  = (const float*)d_in[14];
    const float* rb_wo  = (const float*)d_in[15];
    const float* rb_bo  = (const float*)d_in[16];
    const float* dl_wi  = (const float*)d_in[17];
    const float* dl_bi  = (const float*)d_in[18];
    const float* dl_wo  = (const float*)d_in[19];
    const float* dl_bo  = (const float*)d_in[20];
    float* out = (float*)d_out;

    int n_batch = in_sizes[0] / (TT * FF);
    int tiles = (n_batch + AG - 1) / AG;
    int nblk = tiles < 444 ? tiles : 444;     // 148 SMs x 3 blocks, one wave

    size_t smem = SMEM_FLOATS * sizeof(float);
    static bool attr_done = false;
    if (!attr_done) {
        cudaFuncSetAttribute(sfm_fused,
                             cudaFuncAttributeMaxDynamicSharedMemorySize,
                             (int)smem);
        attr_done = true;
    }

    sfm_fused<<<nblk, 256, smem>>>(ego, nei, border, adp, eff,
                                   an_wi, an_bi, an_wo, an_bo,
                                   rn_wi, rn_bi, rn_wo, rn_bo,
                                   rb_wi, rb_bi, rb_wo, rb_bo,
                                   dl_wi, dl_bi, dl_wo, dl_bo,
                                   out, n_batch);
}

// round 10
// speedup vs baseline: 1.3277x; 1.3277x over previous
#include <cuda_runtime.h>
#include <stdint.h>

#define TT 3
#define FF 17
#define NN 8
#define DT 0.2f
#define EPS 1e-8f
#define EROW 51                // floats per agent in ego (3*17)
#define NROW 136               // floats per agent in nei (8*17)

// Branchless count of sorted thresholds <= x (k in [0,32]), then 1 FMA.
__device__ __forceinline__ float pwl_eval(const float* __restrict__ t,
                                          const float* __restrict__ A,
                                          const float* __restrict__ C,
                                          float x)
{
    int k = 0;
    if (t[15]    <= x) k  = 16;
    if (t[k + 7] <= x) k += 8;
    if (t[k + 3] <= x) k += 4;
    if (t[k + 1] <= x) k += 2;
    if (t[k]     <= x) k += 1;   // k in [0,31]
    if (t[31]    <= x) k += 1;   // all <= x  => k = 32
    return fmaf(A[k], x, C[k]);
}

// ---------------------------------------------------------------------------
// Single fused kernel. Prologue: each block builds the three PWL tables
// (warps 0-2, sort + warp suffix scan) and the dl constants (warp 3) with
// arithmetic IDENTICAL to the former standalone precompute kernel, so the
// numerical results are bit-for-bit the same. Main body: one thread per
// agent, all-scalar front-batched loads (proven R6 structure).
// ---------------------------------------------------------------------------
__global__ void __launch_bounds__(256, 4) sfm_all(
    const float* __restrict__ ego, const float* __restrict__ nei,
    const float* __restrict__ border, const float* __restrict__ adp,
    const float* __restrict__ eff_angle,
    const float* __restrict__ an_wi, const float* __restrict__ an_bi,
    const float* __restrict__ an_wo, const float* __restrict__ an_bo,
    const float* __restrict__ rn_wi, const float* __restrict__ rn_bi,
    const float* __restrict__ rn_wo, const float* __restrict__ rn_bo,
    const float* __restrict__ rb_wi, const float* __restrict__ rb_bi,
    const float* __restrict__ rb_wo, const float* __restrict__ rb_bo,
    const float* __restrict__ dl_wi, const float* __restrict__ dl_bi,
    const float* __restrict__ dl_wo, const float* __restrict__ dl_bo,
    float* __restrict__ out, int n_batch)
{
    __shared__ float st[3][32];
    __shared__ float sA[3][33];
    __shared__ float sC[3][33];
    __shared__ float sdl[8];

    int tid = threadIdx.x;
    int warp = tid >> 5, lane = tid & 31;
    const unsigned FULL = 0xffffffffu;
    const float PINF = __int_as_float(0x7f800000);

    // ---- prologue: build tables in-block (same math as old precompute) ----
    if (warp < 3) {
        const float* wi = (warp == 0) ? an_wi : (warp == 1) ? rn_wi : rb_wi;
        const float* bi = (warp == 0) ? an_bi : (warp == 1) ? rn_bi : rb_bi;
        const float* wo = (warp == 0) ? an_wo : (warp == 1) ? rn_wo : rb_wo;
        const float* bo = (warp == 0) ? an_bo : (warp == 1) ? rn_bo : rb_bo;

        float wiv = wi[lane], biv = bi[lane], wov = wo[lane];
        float bov = bo[0];
        // relu(-(wi*x+bi)) active iff x < t  (wi uniform >= 0)
        float t, slope, icept;
        if (wiv > 0.f) {
            t = -biv / wiv; slope = -wov * wiv; icept = -wov * biv;
        } else if (biv < 0.f) {
            t = PINF; slope = 0.f; icept = -wov * biv;   // always active
        } else {
            t = -PINF; slope = 0.f; icept = 0.f;         // never active
        }

        // rank-sort ascending (ties by lane) via shuffles
        int rank = 0;
#pragma unroll
        for (int i = 0; i < 32; i++) {
            float ti = __shfl_sync(FULL, t, i);
            rank += (ti < t) || (ti == t && i < lane);
        }
        st[warp][rank] = t;
        sA[warp][rank] = slope;    // scratch
        sC[warp][rank] = icept;    // scratch
        __syncwarp();
        float A = sA[warp][lane];
        float C = sC[warp][lane];
        // inclusive suffix scan: A[k] = sum_{j>=k} slope[j], same for C
#pragma unroll
        for (int off = 1; off < 32; off <<= 1) {
            float a2 = __shfl_down_sync(FULL, A, off);
            float c2 = __shfl_down_sync(FULL, C, off);
            if (lane + off < 32) { A += a2; C += c2; }
        }
        C += bov;
        __syncwarp();
        sA[warp][lane] = A;
        sC[warp][lane] = C;
        if (lane == 0) { sA[warp][32] = 0.f; sC[warp][32] = bov; }
    } else if (warp == 3 && lane < 8) {
        // dl MLP on dur[n] (depends only on ego batch row 1)
        const float* e1 = ego + (size_t)1 * EROW;
        float id = e1[(TT - 1) * FF + 8 + lane];
        float dur = 0.f;
#pragma unroll
        for (int t = 0; t < TT; t++) {
            bool found = false;
#pragma unroll
            for (int k = 0; k < 8; k++)
                found = found || (e1[t * FF + 8 + k] == id);
            dur += found ? 1.f : 0.f;
        }
        float acc = dl_bo[0];
#pragma unroll
        for (int j = 0; j < 32; j++) {
            float h = fmaxf(-fmaf(dl_wi[j], dur, dl_bi[j]), 0.f);
            acc = fmaf(dl_wo[j], h, acc);
        }
        sdl[lane] = acc;
    }
    __syncthreads();

    int b = blockIdx.x * 256 + tid;
    if (b >= n_batch) return;

    // ---- FRONT-BATCHED LOADS: issue everything before consuming anything ----
    const float* eg = ego + (size_t)b * EROW + (TT - 1) * FF;
    const float* nb = nei + (size_t)b * NROW;

    float g0 = eg[0], g1 = eg[1], g2 = eg[2], g3 = eg[3], g4 = eg[4], g5 = eg[5];

    float a2[8], a3[8], a4[8], a5[8];
#pragma unroll
    for (int n = 0; n < 8; n++) {
        const float* p = nb + n * FF;
        a2[n] = p[2]; a3[n] = p[3]; a4[n] = p[4]; a5[n] = p[5];
    }

    // ---- compute phase (identical FP ops to the R6-validated kernel) ----
    float einv = rsqrtf(g4 * g4 + g5 * g5);
    float ex = g4 * einv, ey = g5 * einv;
    float na = fmaxf(sqrtf(ex * ex + ey * ey), EPS);
    float thr = eff_angle[0] * na;

    float ax = 0.f, ay = 0.f;

    // f_dest: v34 = (g3, g4); dv = (|v34|, 0)
    {
        float nv = sqrtf(g3 * g3 + g4 * g4);
        float p0 = adp[0], p1 = adp[1];
        float fx = (p1 * nv - g3) / p0;
        float fy = (0.f - g4) / p0;
        float dot = ex * fx + ey * fy;
        float nbn = fmaxf(sqrtf(fx * fx + fy * fy), EPS);
        bool keep = fabsf(dot) > thr * nbn;
        ax += keep ? fx : 0.f;
        ay += keep ? fy : 0.f;
    }

    // neighbors: attr + repu share direction r, so one keep-test covers both
#pragma unroll
    for (int n = 0; n < 8; n++) {
        bool mx = (a2[n] == 0.f), my = (a3[n] == 0.f);
        float rx = a2[n] - g2, ry = a3[n] - g3;
        float rnm = sqrtf(rx * rx + ry * ry);
        float vx = a4[n] * DT, vy = a5[n] * DT;
        float px = rx + vx, py = ry + vy;
        float bbv = sqrtf(rnm + px * px + py * py - vx * vx - vy * vy) * 0.5f;

        float fa = pwl_eval(st[0], sA[0], sC[0], rnm);   // an MLP on r_norm
        float fr = pwl_eval(st[1], sA[1], sC[1], bbv);   // rn MLP on b
        float s = (fa * sdl[n] + fr) / rnm;              // combined scalar factor

        float fxb = mx ? 0.f : rx;
        float fyb = my ? 0.f : ry;
        float dot = ex * fxb + ey * fyb;
        float nbn = sqrtf(fxb * fxb + fyb * fyb);
        bool keep = fabsf(dot) > thr * nbn;
        ax += keep ? s * fxb : 0.f;
        ay += keep ? s * fyb : 0.f;
    }

    // f_bor: y-only vectors, magnitude rb(|rbv|), direction sign(rbv)
    {
        float rbv0 = g3 - border[0];
        float rbv1 = g3 - border[3];
        float rbn0 = fabsf(rbv0), rbn1 = fabsf(rbv1);

        float m0 = pwl_eval(st[2], sA[2], sC[2], rbn0);
        float m1 = pwl_eval(st[2], sA[2], sC[2], rbn1);

        float fy0 = m0 * (rbv0 / rbn0);
        float nbn0 = fmaxf(fabsf(fy0), EPS);
        if (fabsf(ey * fy0) > thr * nbn0) ay += fy0;

        float fy1 = m1 * (rbv1 / rbn1);
        float nbn1 = fmaxf(fabsf(fy1), EPS);
        if (fabsf(ey * fy1) > thr * nbn1) ay += fy1;
    }

    float vxo = g2 + ax * DT;
    float vyo = g3 + ay * DT;
    float sx = g0 + vxo * DT;
    float sy = g1 + vyo * DT;

    float* o = out + (size_t)b * 6;     // scalar stores only
    o[0] = sx; o[1] = sy;
    o[2] = vxo; o[3] = vyo;
    o[4] = ax;  o[5] = ay;
}

extern "C" void kernel_launch(void* const* d_in, const int* in_sizes, int n_in,
                              void* d_out, int out_size)
{
    const float* ego    = (const float*)d_in[0];
    const float* nei    = (const float*)d_in[1];
    const float* border = (const float*)d_in[2];
    const float* adp    = (const float*)d_in[3];
    const float* eff    = (const float*)d_in[4];
    const float* an_wi  = (const float*)d_in[5];
    const float* an_bi  = (const float*)d_in[6];
    const float* an_wo  = (const float*)d_in[7];
    const float* an_bo  = (const float*)d_in[8];
    const float* rn_wi  = (const float*)d_in[9];
    const float* rn_bi  = (const float*)d_in[10];
    const float* rn_wo  = (const float*)d_in[11];
    const float* rn_bo  = (const float*)d_in[12];
    const float* rb_wi  = (const float*)d_in[13];
    const float* rb_bi  = (const float*)d_in[14];
    const float* rb_wo  = (const float*)d_in[15];
    const float* rb_bo  = (const float*)d_in[16];
    const float* dl_wi  = (const float*)d_in[17];
    const float* dl_bi  = (const float*)d_in[18];
    const float* dl_wo  = (const float*)d_in[19];
    const float* dl_bo  = (const float*)d_in[20];
    float* out = (float*)d_out;

    int n_batch = in_sizes[0] / (TT * FF);
    int blocks = (n_batch + 255) / 256;

    sfm_all<<<blocks, 256>>>(ego, nei, border, adp, eff,
                             an_wi, an_bi, an_wo, an_bo,
                             rn_wi, rn_bi, rn_wo, rn_bo,
                             rb_wi, rb_bi, rb_wo, rb_bo,
                             dl_wi, dl_bi, dl_wo, dl_bo,
                             out, n_batch);
}

// round 11
// speedup vs baseline: 1.3435x; 1.0119x over previous
#include <cuda_runtime.h>
#include <stdint.h>

#define TT 3
#define FF 17
#define NN 8
#define DT 0.2f
#define EPS 1e-8f
#define EROW 51                // floats per agent in ego (3*17)
#define NROW 136               // floats per agent in nei (8*17)

// Branchless count of sorted thresholds <= x (k in [0,32]), then 1 FMA.
__device__ __forceinline__ float pwl_eval(const float* __restrict__ t,
                                          const float* __restrict__ A,
                                          const float* __restrict__ C,
                                          float x)
{
    int k = 0;
    if (t[15]    <= x) k  = 16;
    if (t[k + 7] <= x) k += 8;
    if (t[k + 3] <= x) k += 4;
    if (t[k + 1] <= x) k += 2;
    if (t[k]     <= x) k += 1;   // k in [0,31]
    if (t[31]    <= x) k += 1;   // all <= x  => k = 32
    return fmaf(A[k], x, C[k]);
}

// ---------------------------------------------------------------------------
// Single fused kernel (R10 structure). Prologue builds the PWL tables +
// dl constants per block (bit-identical math to the old precompute kernel).
// Hot path: one thread per agent, front-batched loads. nei uses the R1-PROVEN
// parity float2 pattern (nei base is 8B-aligned; 544B row stride keeps agent
// parity fixed; fields 2..5 split as even n: [2,3][4,5], odd n: 2,[3,4],5).
// ego stays SCALAR (ego vectorization is what faulted in R2/R3).
// out uses the R1-proven unconditional float2 stores (24B stride, 8B aligned).
// ---------------------------------------------------------------------------
__global__ void __launch_bounds__(256, 4) sfm_all(
    const float* __restrict__ ego, const float* __restrict__ nei,
    const float* __restrict__ border, const float* __restrict__ adp,
    const float* __restrict__ eff_angle,
    const float* __restrict__ an_wi, const float* __restrict__ an_bi,
    const float* __restrict__ an_wo, const float* __restrict__ an_bo,
    const float* __restrict__ rn_wi, const float* __restrict__ rn_bi,
    const float* __restrict__ rn_wo, const float* __restrict__ rn_bo,
    const float* __restrict__ rb_wi, const float* __restrict__ rb_bi,
    const float* __restrict__ rb_wo, const float* __restrict__ rb_bo,
    const float* __restrict__ dl_wi, const float* __restrict__ dl_bi,
    const float* __restrict__ dl_wo, const float* __restrict__ dl_bo,
    float* __restrict__ out, int n_batch)
{
    __shared__ float st[3][32];
    __shared__ float sA[3][33];
    __shared__ float sC[3][33];
    __shared__ float sdl[8];

    int tid = threadIdx.x;
    int warp = tid >> 5, lane = tid & 31;
    const unsigned FULL = 0xffffffffu;
    const float PINF = __int_as_float(0x7f800000);

    // ---- prologue: build tables in-block (same math as old precompute) ----
    if (warp < 3) {
        const float* wi = (warp == 0) ? an_wi : (warp == 1) ? rn_wi : rb_wi;
        const float* bi = (warp == 0) ? an_bi : (warp == 1) ? rn_bi : rb_bi;
        const float* wo = (warp == 0) ? an_wo : (warp == 1) ? rn_wo : rb_wo;
        const float* bo = (warp == 0) ? an_bo : (warp == 1) ? rn_bo : rb_bo;

        float wiv = wi[lane], biv = bi[lane], wov = wo[lane];
        float bov = bo[0];
        // relu(-(wi*x+bi)) active iff x < t  (wi uniform >= 0)
        float t, slope, icept;
        if (wiv > 0.f) {
            t = -biv / wiv; slope = -wov * wiv; icept = -wov * biv;
        } else if (biv < 0.f) {
            t = PINF; slope = 0.f; icept = -wov * biv;   // always active
        } else {
            t = -PINF; slope = 0.f; icept = 0.f;         // never active
        }

        // rank-sort ascending (ties by lane) via shuffles
        int rank = 0;
#pragma unroll
        for (int i = 0; i < 32; i++) {
            float ti = __shfl_sync(FULL, t, i);
            rank += (ti < t) || (ti == t && i < lane);
        }
        st[warp][rank] = t;
        sA[warp][rank] = slope;    // scratch
        sC[warp][rank] = icept;    // scratch
        __syncwarp();
        float A = sA[warp][lane];
        float C = sC[warp][lane];
        // inclusive suffix scan: A[k] = sum_{j>=k} slope[j], same for C
#pragma unroll
        for (int off = 1; off < 32; off <<= 1) {
            float a2 = __shfl_down_sync(FULL, A, off);
            float c2 = __shfl_down_sync(FULL, C, off);
            if (lane + off < 32) { A += a2; C += c2; }
        }
        C += bov;
        __syncwarp();
        sA[warp][lane] = A;
        sC[warp][lane] = C;
        if (lane == 0) { sA[warp][32] = 0.f; sC[warp][32] = bov; }
    } else if (warp == 3 && lane < 8) {
        // dl MLP on dur[n] (depends only on ego batch row 1)
        const float* e1 = ego + (size_t)1 * EROW;
        float id = e1[(TT - 1) * FF + 8 + lane];
        float dur = 0.f;
#pragma unroll
        for (int t = 0; t < TT; t++) {
            bool found = false;
#pragma unroll
            for (int k = 0; k < 8; k++)
                found = found || (e1[t * FF + 8 + k] == id);
            dur += found ? 1.f : 0.f;
        }
        float acc = dl_bo[0];
#pragma unroll
        for (int j = 0; j < 32; j++) {
            float h = fmaxf(-fmaf(dl_wi[j], dur, dl_bi[j]), 0.f);
            acc = fmaf(dl_wo[j], h, acc);
        }
        sdl[lane] = acc;
    }
    __syncthreads();

    int b = blockIdx.x * 256 + tid;
    if (b >= n_batch) return;

    // ---- FRONT-BATCHED LOADS ----
    const float* eg = ego + (size_t)b * EROW + (TT - 1) * FF;
    const float* nb = nei + (size_t)b * NROW;

    // ego: SCALAR only (vectorized ego faulted in R2/R3)
    float g0 = eg[0], g1 = eg[1], g2 = eg[2], g3 = eg[3], g4 = eg[4], g5 = eg[5];

    // nei: R1-proven parity float2 pattern
    float a2[8], a3[8], a4[8], a5[8];
#pragma unroll
    for (int n = 0; n < 8; n++) {
        const float* p = nb + n * FF;
        if (n & 1) {
            a2[n] = p[2];
            float2 t = *reinterpret_cast<const float2*>(p + 3);
            a3[n] = t.x; a4[n] = t.y;
            a5[n] = p[5];
        } else {
            float2 t = *reinterpret_cast<const float2*>(p + 2);
            float2 u = *reinterpret_cast<const float2*>(p + 4);
            a2[n] = t.x; a3[n] = t.y; a4[n] = u.x; a5[n] = u.y;
        }
    }

    // ---- compute phase (identical FP ops to the validated kernel) ----
    float einv = rsqrtf(g4 * g4 + g5 * g5);
    float ex = g4 * einv, ey = g5 * einv;
    float na = fmaxf(sqrtf(ex * ex + ey * ey), EPS);
    float thr = eff_angle[0] * na;

    float ax = 0.f, ay = 0.f;

    // f_dest: v34 = (g3, g4); dv = (|v34|, 0)
    {
        float nv = sqrtf(g3 * g3 + g4 * g4);
        float p0 = adp[0], p1 = adp[1];
        float fx = (p1 * nv - g3) / p0;
        float fy = (0.f - g4) / p0;
        float dot = ex * fx + ey * fy;
        float nbn = fmaxf(sqrtf(fx * fx + fy * fy), EPS);
        bool keep = fabsf(dot) > thr * nbn;
        ax += keep ? fx : 0.f;
        ay += keep ? fy : 0.f;
    }

    // neighbors: attr + repu share direction r, so one keep-test covers both
#pragma unroll
    for (int n = 0; n < 8; n++) {
        bool mx = (a2[n] == 0.f), my = (a3[n] == 0.f);
        float rx = a2[n] - g2, ry = a3[n] - g3;
        float rnm = sqrtf(rx * rx + ry * ry);
        float vx = a4[n] * DT, vy = a5[n] * DT;
        float px = rx + vx, py = ry + vy;
        float bbv = sqrtf(rnm + px * px + py * py - vx * vx - vy * vy) * 0.5f;

        float fa = pwl_eval(st[0], sA[0], sC[0], rnm);   // an MLP on r_norm
        float fr = pwl_eval(st[1], sA[1], sC[1], bbv);   // rn MLP on b
        float s = (fa * sdl[n] + fr) / rnm;              // combined scalar factor

        float fxb = mx ? 0.f : rx;
        float fyb = my ? 0.f : ry;
        float dot = ex * fxb + ey * fyb;
        float nbn = sqrtf(fxb * fxb + fyb * fyb);
        bool keep = fabsf(dot) > thr * nbn;
        ax += keep ? s * fxb : 0.f;
        ay += keep ? s * fyb : 0.f;
    }

    // f_bor: y-only vectors, magnitude rb(|rbv|), direction sign(rbv)
    {
        float rbv0 = g3 - border[0];
        float rbv1 = g3 - border[3];
        float rbn0 = fabsf(rbv0), rbn1 = fabsf(rbv1);

        float m0 = pwl_eval(st[2], sA[2], sC[2], rbn0);
        float m1 = pwl_eval(st[2], sA[2], sC[2], rbn1);

        float fy0 = m0 * (rbv0 / rbn0);
        float nbn0 = fmaxf(fabsf(fy0), EPS);
        if (fabsf(ey * fy0) > thr * nbn0) ay += fy0;

        float fy1 = m1 * (rbv1 / rbn1);
        float nbn1 = fmaxf(fabsf(fy1), EPS);
        if (fabsf(ey * fy1) > thr * nbn1) ay += fy1;
    }

    float vxo = g2 + ax * DT;
    float vyo = g3 + ay * DT;
    float sx = g0 + vxo * DT;
    float sy = g1 + vyo * DT;

    // out: R1-proven float2 stores (24B stride, base 8B aligned)
    float2* o = reinterpret_cast<float2*>(out + (size_t)b * 6);
    o[0] = make_float2(sx, sy);
    o[1] = make_float2(vxo, vyo);
    o[2] = make_float2(ax, ay);
}

extern "C" void kernel_launch(void* const* d_in, const int* in_sizes, int n_in,
                              void* d_out, int out_size)
{
    const float* ego    = (const float*)d_in[0];
    const float* nei    = (const float*)d_in[1];
    const float* border = (const float*)d_in[2];
    const float* adp    = (const float*)d_in[3];
    const float* eff    = (const float*)d_in[4];
    const float* an_wi  = (const float*)d_in[5];
    const float* an_bi  = (const float*)d_in[6];
    const float* an_wo  = (const float*)d_in[7];
    const float* an_bo  = (const float*)d_in[8];
    const float* rn_wi  = (const float*)d_in[9];
    const float* rn_bi  = (const float*)d_in[10];
    const float* rn_wo  = (const float*)d_in[11];
    const float* rn_bo  = (const float*)d_in[12];
    const float* rb_wi  = (const float*)d_in[13];
    const float* rb_bi  = (const float*)d_in[14];
    const float* rb_wo  = (const float*)d_in[15];
    const float* rb_bo  = (const float*)d_in[16];
    const float* dl_wi  = (const float*)d_in[17];
    const float* dl_bi  = (const float*)d_in[18];
    const float* dl_wo  = (const float*)d_in[19];
    const float* dl_bo  = (const float*)d_in[20];
    float* out = (float*)d_out;

    int n_batch = in_sizes[0] / (TT * FF);
    int blocks = (n_batch + 255) / 256;

    sfm_all<<<blocks, 256>>>(ego, nei, border, adp, eff,
                             an_wi, an_bi, an_wo, an_bo,
                             rn_wi, rn_bi, rn_wo, rn_bo,
                             rb_wi, rb_bi, rb_wo, rb_bo,
                             dl_wi, dl_bi, dl_wo, dl_bo,
                             out, n_batch);
}